// round 9
// baseline (speedup 1.0000x reference)
#include <cuda_runtime.h>
#include <cuda_fp16.h>
#include <cstdint>

// ---------------------------------------------------------------------------
// Problem constants
// ---------------------------------------------------------------------------
#define B_     8
#define CIN    128
#define H_     64
#define W_     64
#define COUT   128
#define KH     4
#define KW     4
#define KK     16
#define HO     61
#define WO     61
#define PIX    (HO*WO)            // 3721
#define M_TOT  (B_*PIX)           // 29768
#define M_PAD  29824              // 233 * 128
#define MT     233                // M tiles of 128
#define KDIM   2048
#define NCHUNK 32                 // K chunks of 64 halves

// ---------------------------------------------------------------------------
// Scratch (device globals; zero-initialized; pad rows of g_A stay 0 forever)
// ---------------------------------------------------------------------------
__device__ __half g_inT[(size_t)B_*H_*W_*CIN];     // NHWC input fp16, 8.4 MB
__device__ __half g_A[(size_t)M_PAD*KDIM];         // sampled matrix fp16
__device__ __half g_W2[(size_t)COUT*KDIM];         // flipped/reordered weights fp16

// ---------------------------------------------------------------------------
// Helpers
// ---------------------------------------------------------------------------
__device__ __forceinline__ uint32_t smem_to_u32(const void* smem_ptr) {
    uint32_t addr;
    asm("{ .reg .u64 tmp; cvta.to.shared.u64 tmp, %1; cvt.u32.u64 %0, tmp; }"
        : "=r"(addr) : "l"(smem_ptr));
    return addr;
}
__device__ __forceinline__ void cp_async16(uint32_t smem_addr, const void* gptr) {
    asm volatile("cp.async.cg.shared.global [%0], [%1], 16;\n"
                 :: "r"(smem_addr), "l"(gptr));
}
#define CP_COMMIT() asm volatile("cp.async.commit_group;\n" ::: "memory")
#define CP_WAIT0()  asm volatile("cp.async.wait_group 0;\n" ::: "memory")
#define CP_WAIT1()  asm volatile("cp.async.wait_group 1;\n" ::: "memory")

__device__ __forceinline__ void ldmatrix_x4(uint32_t* r, uint32_t addr) {
    asm volatile("ldmatrix.sync.aligned.m8n8.x4.shared.b16 {%0,%1,%2,%3}, [%4];"
                 : "=r"(r[0]), "=r"(r[1]), "=r"(r[2]), "=r"(r[3]) : "r"(addr));
}
__device__ __forceinline__ void mma16816(float* c, const uint32_t* a, const uint32_t* b) {
    asm volatile(
        "mma.sync.aligned.m16n8k16.row.col.f32.f16.f16.f32 "
        "{%0,%1,%2,%3}, {%4,%5,%6,%7}, {%8,%9}, {%0,%1,%2,%3};"
        : "+f"(c[0]), "+f"(c[1]), "+f"(c[2]), "+f"(c[3])
        : "r"(a[0]), "r"(a[1]), "r"(a[2]), "r"(a[3]), "r"(b[0]), "r"(b[1]));
}

// ---------------------------------------------------------------------------
// Kernel 1: NCHW(f32) -> NHWC(f16) transpose of input
// ---------------------------------------------------------------------------
__global__ void transpose_kernel(const float* __restrict__ in) {
    __shared__ float tile[32][33];
    int id = blockIdx.x;
    int bh = id >> 3;
    int t  = id & 7;
    int c0 = (t >> 1) * 32;
    int x0 = (t & 1) * 32;
    int b = bh >> 6, y = bh & 63;
    int tx = threadIdx.x, ty = threadIdx.y;

    const float* src = in + (((size_t)(b * CIN + c0) * H_ + y) * W_ + x0);
#pragma unroll
    for (int j = 0; j < 4; j++) {
        int c = ty * 4 + j;
        tile[c][tx] = src[(size_t)c * (H_ * W_) + tx];
    }
    __syncthreads();
    __half* dst = g_inT + (((size_t)(b * H_ + y) * W_ + x0) * CIN + c0);
#pragma unroll
    for (int j = 0; j < 4; j++) {
        int xi = ty * 4 + j;
        dst[(size_t)xi * CIN + tx] = __float2half(tile[tx][xi]);
    }
}

// ---------------------------------------------------------------------------
// Kernel 2: weight flip + reorder to W2[co][k*128+ci], fp16
// ---------------------------------------------------------------------------
__global__ void prep_weight_kernel(const float* __restrict__ w) {
    int idx = blockIdx.x * 256 + threadIdx.x;
    if (idx >= COUT * KDIM) return;
    int o  = idx >> 11;
    int kk = idx & 2047;
    int k  = kk >> 7;
    int ci = kk & 127;
    int ki = k >> 2, kj = k & 3;
    float val = w[(((size_t)o * CIN + ci) * KH + (KH - 1 - ki)) * KW + (KW - 1 - kj)];
    g_W2[idx] = __float2half(val);
}

// ---------------------------------------------------------------------------
// Kernel 3: bilinear sampling (fp16 gathers) -> A[m][k*128+ci] fp16
// Block = 512 thr = 16 warps; warp = tap, 32 consecutive pixels.
// ---------------------------------------------------------------------------
__global__ __launch_bounds__(512) void sample_kernel(const float* __restrict__ offset,
                                                     const float* __restrict__ mask) {
    __shared__ int4 pix[32];
    const int tid  = threadIdx.x;
    const int k    = tid >> 5;           // warp = tap
    const int lane = tid & 31;
    const int m0   = blockIdx.x * 32;

    if (tid < 32) {
        int m = m0 + tid;
        int4 pd;
        if (m < M_TOT) {
            int b   = m / PIX;
            int rem = m - b * PIX;
            pd.x = b; pd.y = rem / WO; pd.z = rem - (rem / WO) * WO; pd.w = 1;
        } else {
            pd.w = 0; pd.x = pd.y = pd.z = 0;
        }
        pix[tid] = pd;
    }
    __syncthreads();

    const int ki = k >> 2, kj = k & 3;
    const int ci0 = lane * 4;

#pragma unroll 4
    for (int i = 0; i < 32; ++i) {
        int4 pd = pix[i];
        if (!pd.w) continue;             // warp-uniform
        int m = m0 + i;
        int b = pd.x, oy = pd.y, ox = pd.z;

        int obase = ((b * (2 * KK) + 2 * k) * HO + oy) * WO + ox;
        float dy  = __ldg(offset + obase);
        float dx  = __ldg(offset + obase + PIX);
        float msk = __ldg(mask + ((b * KK + k) * HO + oy) * WO + ox);

        float y = dy + (float)(ki + oy);
        float x = dx + (float)(kj + ox);
        float y0f = floorf(y), x0f = floorf(x);
        float wy = y - y0f, wx = x - x0f;
        int y0 = (int)y0f, x0 = (int)x0f;

        bool vy0 = (y0 >= 0) && (y0 < H_);
        bool vy1 = (y0 >= -1) && (y0 < H_ - 1);
        bool vx0 = (x0 >= 0) && (x0 < W_);
        bool vx1 = (x0 >= -1) && (x0 < W_ - 1);

        float w00 = (vy0 && vx0) ? (1.f - wy) * (1.f - wx) * msk : 0.f;
        float w01 = (vy0 && vx1) ? (1.f - wy) * wx * msk : 0.f;
        float w10 = (vy1 && vx0) ? wy * (1.f - wx) * msk : 0.f;
        float w11 = (vy1 && vx1) ? wy * wx * msk : 0.f;

        int y0c = min(max(y0, 0), H_ - 1);
        int y1c = min(max(y0 + 1, 0), H_ - 1);
        int x0c = min(max(x0, 0), W_ - 1);
        int x1c = min(max(x0 + 1, 0), W_ - 1);

        const __half* basep = g_inT + (size_t)b * (H_ * W_ * CIN) + ci0;
        uint2 q00 = *(const uint2*)(basep + ((size_t)y0c * W_ + x0c) * CIN);
        uint2 q01 = *(const uint2*)(basep + ((size_t)y0c * W_ + x1c) * CIN);
        uint2 q10 = *(const uint2*)(basep + ((size_t)y1c * W_ + x0c) * CIN);
        uint2 q11 = *(const uint2*)(basep + ((size_t)y1c * W_ + x1c) * CIN);

        float2 a0 = __half22float2(*reinterpret_cast<__half2*>(&q00.x));
        float2 a1 = __half22float2(*reinterpret_cast<__half2*>(&q00.y));
        float2 b0 = __half22float2(*reinterpret_cast<__half2*>(&q01.x));
        float2 b1 = __half22float2(*reinterpret_cast<__half2*>(&q01.y));
        float2 c0 = __half22float2(*reinterpret_cast<__half2*>(&q10.x));
        float2 c1 = __half22float2(*reinterpret_cast<__half2*>(&q10.y));
        float2 d0 = __half22float2(*reinterpret_cast<__half2*>(&q11.x));
        float2 d1 = __half22float2(*reinterpret_cast<__half2*>(&q11.y));

        float s0 = w00 * a0.x + w01 * b0.x + w10 * c0.x + w11 * d0.x;
        float s1 = w00 * a0.y + w01 * b0.y + w10 * c0.y + w11 * d0.y;
        float s2 = w00 * a1.x + w01 * b1.x + w10 * c1.x + w11 * d1.x;
        float s3 = w00 * a1.y + w01 * b1.y + w10 * c1.y + w11 * d1.y;

        __half2 h0 = __floats2half2_rn(s0, s1);
        __half2 h1 = __floats2half2_rn(s2, s3);
        uint2 packed;
        packed.x = *reinterpret_cast<uint32_t*>(&h0);
        packed.y = *reinterpret_cast<uint32_t*>(&h1);
        *reinterpret_cast<uint2*>(g_A + (size_t)m * KDIM + k * 128 + ci0) = packed;
    }
}

// ---------------------------------------------------------------------------
// Kernel 4: GEMM  out[m][co] = A[m][:] . W2[co][:]  (+bias)
// 512 threads, 16 warps, CTA 128x128, warp tile 32x32 -> 32 warps/SM at occ 2.
// 3-stage cp.async pipeline, K-chunk 64.
// ---------------------------------------------------------------------------
#define STAGE_BYTES 32768
#define GEMM_SMEM   98304

__global__ __launch_bounds__(512, 2) void gemm_kernel(const float* __restrict__ bias,
                                                      float* __restrict__ out) {
    extern __shared__ char smem[];
    const uint32_t smem_base = smem_to_u32(smem);
    const int tid  = threadIdx.x;
    const int wid  = tid >> 5;
    const int lane = tid & 31;
    const int m0   = blockIdx.x * 128;
    const int m_warp = (wid >> 2) * 32;   // 0,32,64,96
    const int n_warp = (wid & 3) * 32;    // 0,32,64,96

    float acc[2][4][4];
#pragma unroll
    for (int i = 0; i < 2; i++)
#pragma unroll
        for (int j = 0; j < 4; j++)
#pragma unroll
            for (int r = 0; r < 4; r++) acc[i][j][r] = 0.f;

    auto load_chunk = [&](int kc, int s) {
        uint32_t base = smem_base + s * STAGE_BYTES;
#pragma unroll
        for (int i = 0; i < 2; i++) {
            int sidx = tid + i * 512;          // 0..1023
            int row  = sidx >> 3;
            int cj   = sidx & 7;
            uint32_t off = (uint32_t)(row * 128 + ((cj ^ (row & 7)) << 4));
            cp_async16(base + off,
                       g_A + (size_t)(m0 + row) * KDIM + kc * 64 + cj * 8);
            cp_async16(base + 16384 + off,
                       g_W2 + (size_t)row * KDIM + kc * 64 + cj * 8);
        }
        CP_COMMIT();
    };

    load_chunk(0, 0);
    load_chunk(1, 1);

    int s = 0;
    for (int kc = 0; kc < NCHUNK; ++kc) {
        if (kc == NCHUNK - 1) { CP_WAIT0(); } else { CP_WAIT1(); }
        __syncthreads();
        if (kc + 2 < NCHUNK) {
            int s2 = s + 2; if (s2 >= 3) s2 -= 3;
            load_chunk(kc + 2, s2);
        }

        uint32_t aBase = smem_base + s * STAGE_BYTES;
        uint32_t bBase = aBase + 16384;
#pragma unroll
        for (int ks = 0; ks < 4; ++ks) {
            // A frags: 2 x ldmatrix_x4 (rows m_warp..+31)
            uint32_t afrag[2][4];
#pragma unroll
            for (int mi = 0; mi < 2; mi++) {
                int row = m_warp + mi * 16 + (lane & 15);
                int ch  = 2 * ks + (lane >> 4);
                ldmatrix_x4(afrag[mi], aBase + row * 128 + ((ch ^ (row & 7)) << 4));
            }
            // B frags: 2 x ldmatrix_x4, each covering 2 n8 fragments
            uint32_t bfrag[4][2];
#pragma unroll
            for (int nh = 0; nh < 2; nh++) {
                int row = n_warp + nh * 16 + ((lane >> 4) << 3) + (lane & 7);
                int ch  = 2 * ks + ((lane >> 3) & 1);
                uint32_t r4[4];
                ldmatrix_x4(r4, bBase + row * 128 + ((ch ^ (row & 7)) << 4));
                bfrag[nh * 2][0]     = r4[0];
                bfrag[nh * 2][1]     = r4[1];
                bfrag[nh * 2 + 1][0] = r4[2];
                bfrag[nh * 2 + 1][1] = r4[3];
            }
#pragma unroll
            for (int mi = 0; mi < 2; mi++)
#pragma unroll
                for (int ni = 0; ni < 4; ni++)
                    mma16816(acc[mi][ni], afrag[mi], bfrag[ni]);
        }
        if (++s == 3) s = 0;
    }

    // ---- epilogue: stage tile in smem [128][129] f32, then coalesced writes
    __syncthreads();
    float* so = reinterpret_cast<float*>(smem);
#pragma unroll
    for (int mi = 0; mi < 2; mi++) {
#pragma unroll
        for (int ni = 0; ni < 4; ni++) {
            int r0 = m_warp + mi * 16 + (lane >> 2);
            int c0 = n_warp + ni * 8 + (lane & 3) * 2;
            so[r0 * 129 + c0]           = acc[mi][ni][0];
            so[r0 * 129 + c0 + 1]       = acc[mi][ni][1];
            so[(r0 + 8) * 129 + c0]     = acc[mi][ni][2];
            so[(r0 + 8) * 129 + c0 + 1] = acc[mi][ni][3];
        }
    }
    __syncthreads();

#pragma unroll 8
    for (int i = tid; i < 128 * 128; i += 512) {
        int co = i >> 7;
        int ml = i & 127;
        int m  = m0 + ml;
        if (m < M_TOT) {
            int b   = m / PIX;
            int rem = m - b * PIX;
            out[(size_t)b * (COUT * PIX) + (size_t)co * PIX + rem] =
                so[ml * 129 + co] + __ldg(bias + co);
        }
    }
}

// ---------------------------------------------------------------------------
// Launch
// ---------------------------------------------------------------------------
extern "C" void kernel_launch(void* const* d_in, const int* in_sizes, int n_in,
                              void* d_out, int out_size) {
    const float* input  = (const float*)d_in[0];
    const float* offset = (const float*)d_in[1];
    const float* mask   = (const float*)d_in[2];
    const float* weight = (const float*)d_in[3];
    const float* bias   = (const float*)d_in[4];
    float* out = (float*)d_out;

    cudaFuncSetAttribute(gemm_kernel,
                         cudaFuncAttributeMaxDynamicSharedMemorySize, GEMM_SMEM);

    transpose_kernel<<<B_ * H_ * 8, dim3(32, 8)>>>(input);
    prep_weight_kernel<<<(COUT * KDIM + 255) / 256, 256>>>(weight);
    sample_kernel<<<(M_TOT + 31) / 32, 512>>>(offset, mask);
    gemm_kernel<<<MT, 512, GEMM_SMEM>>>(bias, out);
}

// round 10
// speedup vs baseline: 1.3300x; 1.3300x over previous
#include <cuda_runtime.h>
#include <cuda_fp16.h>
#include <cstdint>

// ---------------------------------------------------------------------------
// Problem constants
// ---------------------------------------------------------------------------
#define B_     8
#define CIN    128
#define H_     64
#define W_     64
#define COUT   128
#define KH     4
#define KW     4
#define KK     16
#define HO     61
#define WO     61
#define PIX    (HO*WO)            // 3721
#define M_TOT  (B_*PIX)           // 29768
#define M_PAD  29824              // 233 * 128
#define MT     233                // M tiles of 128
#define KDIM   2048
#define NCHUNK 32                 // K chunks of 64 halves
#define NTASK  (M_TOT*KK)         // 476288

// ---------------------------------------------------------------------------
// Scratch (device globals; zero-initialized; pad rows of g_A stay 0 forever)
// ---------------------------------------------------------------------------
__device__ __half g_inT[(size_t)B_*H_*W_*CIN];     // NHWC input fp16, 8.4 MB
__device__ __half g_A[(size_t)M_PAD*KDIM];         // sampled matrix fp16
__device__ __half g_W2[(size_t)COUT*KDIM];         // flipped/reordered weights fp16
__device__ uint4  g_wdesc[NTASK];                  // per-(k,m): 4 fp32 bilinear weights
__device__ uint2  g_adesc[NTASK];                  // per-(k,m): {addr00 bytes, dys<<16|dxs}

// ---------------------------------------------------------------------------
// Helpers
// ---------------------------------------------------------------------------
__device__ __forceinline__ uint32_t smem_to_u32(const void* smem_ptr) {
    uint32_t addr;
    asm("{ .reg .u64 tmp; cvta.to.shared.u64 tmp, %1; cvt.u32.u64 %0, tmp; }"
        : "=r"(addr) : "l"(smem_ptr));
    return addr;
}
__device__ __forceinline__ void cp_async16(uint32_t smem_addr, const void* gptr) {
    asm volatile("cp.async.cg.shared.global [%0], [%1], 16;\n"
                 :: "r"(smem_addr), "l"(gptr));
}
#define CP_COMMIT() asm volatile("cp.async.commit_group;\n" ::: "memory")
#define CP_WAIT0()  asm volatile("cp.async.wait_group 0;\n" ::: "memory")
#define CP_WAIT1()  asm volatile("cp.async.wait_group 1;\n" ::: "memory")

__device__ __forceinline__ void ldmatrix_x4(uint32_t* r, uint32_t addr) {
    asm volatile("ldmatrix.sync.aligned.m8n8.x4.shared.b16 {%0,%1,%2,%3}, [%4];"
                 : "=r"(r[0]), "=r"(r[1]), "=r"(r[2]), "=r"(r[3]) : "r"(addr));
}
__device__ __forceinline__ void ldmatrix_x2(uint32_t* r, uint32_t addr) {
    asm volatile("ldmatrix.sync.aligned.m8n8.x2.shared.b16 {%0,%1}, [%2];"
                 : "=r"(r[0]), "=r"(r[1]) : "r"(addr));
}
__device__ __forceinline__ void mma16816(float* c, const uint32_t* a, const uint32_t* b) {
    asm volatile(
        "mma.sync.aligned.m16n8k16.row.col.f32.f16.f16.f32 "
        "{%0,%1,%2,%3}, {%4,%5,%6,%7}, {%8,%9}, {%0,%1,%2,%3};"
        : "+f"(c[0]), "+f"(c[1]), "+f"(c[2]), "+f"(c[3])
        : "r"(a[0]), "r"(a[1]), "r"(a[2]), "r"(a[3]), "r"(b[0]), "r"(b[1]));
}

// ---------------------------------------------------------------------------
// Kernel 1: NCHW(f32) -> NHWC(f16) transpose of input
// ---------------------------------------------------------------------------
__global__ void transpose_kernel(const float* __restrict__ in) {
    __shared__ float tile[32][33];
    int id = blockIdx.x;
    int bh = id >> 3;
    int t  = id & 7;
    int c0 = (t >> 1) * 32;
    int x0 = (t & 1) * 32;
    int b = bh >> 6, y = bh & 63;
    int tx = threadIdx.x, ty = threadIdx.y;

    const float* src = in + (((size_t)(b * CIN + c0) * H_ + y) * W_ + x0);
#pragma unroll
    for (int j = 0; j < 4; j++) {
        int c = ty * 4 + j;
        tile[c][tx] = src[(size_t)c * (H_ * W_) + tx];
    }
    __syncthreads();
    __half* dst = g_inT + (((size_t)(b * H_ + y) * W_ + x0) * CIN + c0);
#pragma unroll
    for (int j = 0; j < 4; j++) {
        int xi = ty * 4 + j;
        dst[(size_t)xi * CIN + tx] = __float2half(tile[tx][xi]);
    }
}

// ---------------------------------------------------------------------------
// Kernel 2: weight flip + reorder to W2[co][k*128+ci], fp16
// ---------------------------------------------------------------------------
__global__ void prep_weight_kernel(const float* __restrict__ w) {
    int idx = blockIdx.x * 256 + threadIdx.x;
    if (idx >= COUT * KDIM) return;
    int o  = idx >> 11;
    int kk = idx & 2047;
    int k  = kk >> 7;
    int ci = kk & 127;
    int ki = k >> 2, kj = k & 3;
    float val = w[(((size_t)o * CIN + ci) * KH + (KH - 1 - ki)) * KW + (KW - 1 - kj)];
    g_W2[idx] = __float2half(val);
}

// ---------------------------------------------------------------------------
// Kernel 2b: precompute bilinear descriptors, k-major (coalesced both sides)
// tid = k*M_TOT + m
// ---------------------------------------------------------------------------
__global__ void precompute_kernel(const float* __restrict__ offset,
                                  const float* __restrict__ mask) {
    int tid = blockIdx.x * 256 + threadIdx.x;
    if (tid >= NTASK) return;
    int k = tid / M_TOT;
    int m = tid - k * M_TOT;
    int b   = m / PIX;
    int rem = m - b * PIX;
    int oy  = rem / WO;
    int ox  = rem - oy * WO;
    int ki = k >> 2, kj = k & 3;

    int obase = ((b * (2 * KK) + 2 * k) * HO + oy) * WO + ox;
    float dy  = __ldg(offset + obase);
    float dx  = __ldg(offset + obase + PIX);
    float msk = __ldg(mask + ((b * KK + k) * HO + oy) * WO + ox);

    float y = dy + (float)(ki + oy);
    float x = dx + (float)(kj + ox);
    float y0f = floorf(y), x0f = floorf(x);
    float wy = y - y0f, wx = x - x0f;
    int y0 = (int)y0f, x0 = (int)x0f;

    bool vy0 = (y0 >= 0) && (y0 < H_);
    bool vy1 = (y0 >= -1) && (y0 < H_ - 1);
    bool vx0 = (x0 >= 0) && (x0 < W_);
    bool vx1 = (x0 >= -1) && (x0 < W_ - 1);

    float w00 = (vy0 && vx0) ? (1.f - wy) * (1.f - wx) * msk : 0.f;
    float w01 = (vy0 && vx1) ? (1.f - wy) * wx * msk : 0.f;
    float w10 = (vy1 && vx0) ? wy * (1.f - wx) * msk : 0.f;
    float w11 = (vy1 && vx1) ? wy * wx * msk : 0.f;

    int y0c = min(max(y0, 0), H_ - 1);
    int y1c = min(max(y0 + 1, 0), H_ - 1);
    int x0c = min(max(x0, 0), W_ - 1);
    int x1c = min(max(x0 + 1, 0), W_ - 1);

    uint4 wd;
    wd.x = __float_as_uint(w00);
    wd.y = __float_as_uint(w01);
    wd.z = __float_as_uint(w10);
    wd.w = __float_as_uint(w11);
    g_wdesc[tid] = wd;

    uint32_t addr00 = (uint32_t)((y0c * W_ + x0c) * CIN * 2);
    uint32_t dxs = (uint32_t)((x1c - x0c) * CIN * 2);        // 0 or 256
    uint32_t dys = (uint32_t)((y1c - y0c) * W_ * CIN * 2);   // 0 or 16384
    uint2 ad;
    ad.x = addr00;
    ad.y = (dys << 16) | dxs;
    g_adesc[tid] = ad;
}

// ---------------------------------------------------------------------------
// Kernel 3: lean bilinear sampler -> A[m][k*128+ci] fp16
// Block 512 = 16 warps; warp = tap k, 32 consecutive pixels.
// Per task: 2 uniform desc loads + 4 fp16 gathers + fp32 interp + store.
// ---------------------------------------------------------------------------
__global__ __launch_bounds__(512) void sample_kernel() {
    __shared__ uint32_t pixbase[32];   // image base byte offset, or 0xFFFFFFFF invalid
    const int tid  = threadIdx.x;
    const int k    = tid >> 5;
    const int lane = tid & 31;
    const int m0   = blockIdx.x * 32;

    if (tid < 32) {
        int m = m0 + tid;
        pixbase[tid] = (m < M_TOT) ?
            (uint32_t)((m / PIX) * (H_ * W_ * CIN * 2)) : 0xFFFFFFFFu;
    }
    __syncthreads();

    const char* imgC = (const char*)g_inT + lane * 8;   // +ci0*2
    const int dbase  = k * M_TOT + m0;

#pragma unroll 4
    for (int i = 0; i < 32; ++i) {
        uint32_t ib = pixbase[i];
        if (ib == 0xFFFFFFFFu) continue;     // warp-uniform
        int m = m0 + i;

        uint4 wd = __ldg(&g_wdesc[dbase + i]);
        uint2 ad = __ldg(&g_adesc[dbase + i]);
        uint32_t a00 = ad.x;
        uint32_t dxs = ad.y & 0xFFFFu;
        uint32_t dys = ad.y >> 16;

        const char* p = imgC + ib;
        uint2 q00 = *(const uint2*)(p + a00);
        uint2 q01 = *(const uint2*)(p + a00 + dxs);
        uint2 q10 = *(const uint2*)(p + a00 + dys);
        uint2 q11 = *(const uint2*)(p + a00 + dys + dxs);

        float w00 = __uint_as_float(wd.x);
        float w01 = __uint_as_float(wd.y);
        float w10 = __uint_as_float(wd.z);
        float w11 = __uint_as_float(wd.w);

        float2 a0 = __half22float2(*reinterpret_cast<__half2*>(&q00.x));
        float2 a1 = __half22float2(*reinterpret_cast<__half2*>(&q00.y));
        float2 b0 = __half22float2(*reinterpret_cast<__half2*>(&q01.x));
        float2 b1 = __half22float2(*reinterpret_cast<__half2*>(&q01.y));
        float2 c0 = __half22float2(*reinterpret_cast<__half2*>(&q10.x));
        float2 c1 = __half22float2(*reinterpret_cast<__half2*>(&q10.y));
        float2 d0 = __half22float2(*reinterpret_cast<__half2*>(&q11.x));
        float2 d1 = __half22float2(*reinterpret_cast<__half2*>(&q11.y));

        float s0 = w00 * a0.x + w01 * b0.x + w10 * c0.x + w11 * d0.x;
        float s1 = w00 * a0.y + w01 * b0.y + w10 * c0.y + w11 * d0.y;
        float s2 = w00 * a1.x + w01 * b1.x + w10 * c1.x + w11 * d1.x;
        float s3 = w00 * a1.y + w01 * b1.y + w10 * c1.y + w11 * d1.y;

        __half2 h0 = __floats2half2_rn(s0, s1);
        __half2 h1 = __floats2half2_rn(s2, s3);
        uint2 packed;
        packed.x = *reinterpret_cast<uint32_t*>(&h0);
        packed.y = *reinterpret_cast<uint32_t*>(&h1);
        *reinterpret_cast<uint2*>(g_A + (size_t)m * KDIM + k * 128 + lane * 4) = packed;
    }
}

// ---------------------------------------------------------------------------
// Kernel 4: GEMM (R6 config — measured 54.4us)
// 256 thr, warp tile 64x32, K-chunk 64, 3-stage cp.async, one sync/iter.
// ---------------------------------------------------------------------------
#define STAGE_BYTES 32768
#define GEMM_SMEM   98304

__global__ __launch_bounds__(256) void gemm_kernel(const float* __restrict__ bias,
                                                   float* __restrict__ out) {
    extern __shared__ char smem[];
    const uint32_t smem_base = smem_to_u32(smem);
    const int tid  = threadIdx.x;
    const int wid  = tid >> 5;
    const int lane = tid & 31;
    const int m0   = blockIdx.x * 128;
    const int m_warp = (wid >> 2) * 64;   // 0 or 64
    const int n_warp = (wid & 3) * 32;    // 0,32,64,96

    float acc[4][4][4];
#pragma unroll
    for (int i = 0; i < 4; i++)
#pragma unroll
        for (int j = 0; j < 4; j++)
#pragma unroll
            for (int r = 0; r < 4; r++) acc[i][j][r] = 0.f;

    auto load_chunk = [&](int kc, int s) {
        uint32_t base = smem_base + s * STAGE_BYTES;
#pragma unroll
        for (int i = 0; i < 4; i++) {
            int sidx = tid + i * 256;          // 0..1023
            int row  = sidx >> 3;
            int cj   = sidx & 7;
            uint32_t off = (uint32_t)(row * 128 + ((cj ^ (row & 7)) << 4));
            cp_async16(base + off,
                       g_A + (size_t)(m0 + row) * KDIM + kc * 64 + cj * 8);
            cp_async16(base + 16384 + off,
                       g_W2 + (size_t)row * KDIM + kc * 64 + cj * 8);
        }
        CP_COMMIT();
    };

    load_chunk(0, 0);
    load_chunk(1, 1);

    int s = 0;
    for (int kc = 0; kc < NCHUNK; ++kc) {
        if (kc == NCHUNK - 1) { CP_WAIT0(); } else { CP_WAIT1(); }
        __syncthreads();
        if (kc + 2 < NCHUNK) {
            int s2 = s + 2; if (s2 >= 3) s2 -= 3;
            load_chunk(kc + 2, s2);
        }

        uint32_t aBase = smem_base + s * STAGE_BYTES;
        uint32_t bBase = aBase + 16384;
#pragma unroll
        for (int ks = 0; ks < 4; ++ks) {
            uint32_t afrag[4][4];
#pragma unroll
            for (int mi = 0; mi < 4; mi++) {
                int row = m_warp + mi * 16 + (lane & 15);
                int ch  = 2 * ks + (lane >> 4);
                ldmatrix_x4(afrag[mi], aBase + row * 128 + ((ch ^ (row & 7)) << 4));
            }
            uint32_t bfrag[4][2];
#pragma unroll
            for (int ni = 0; ni < 4; ni++) {
                int row = n_warp + ni * 8 + (lane & 7);
                int ch  = 2 * ks + ((lane >> 3) & 1);
                ldmatrix_x2(bfrag[ni], bBase + row * 128 + ((ch ^ (row & 7)) << 4));
            }
#pragma unroll
            for (int mi = 0; mi < 4; mi++)
#pragma unroll
                for (int ni = 0; ni < 4; ni++)
                    mma16816(acc[mi][ni], afrag[mi], bfrag[ni]);
        }
        if (++s == 3) s = 0;
    }

    // ---- epilogue: stage tile in smem [128][129] f32, then coalesced writes
    __syncthreads();
    float* so = reinterpret_cast<float*>(smem);
#pragma unroll
    for (int mi = 0; mi < 4; mi++) {
#pragma unroll
        for (int ni = 0; ni < 4; ni++) {
            int r0 = m_warp + mi * 16 + (lane >> 2);
            int c0 = n_warp + ni * 8 + (lane & 3) * 2;
            so[r0 * 129 + c0]           = acc[mi][ni][0];
            so[r0 * 129 + c0 + 1]       = acc[mi][ni][1];
            so[(r0 + 8) * 129 + c0]     = acc[mi][ni][2];
            so[(r0 + 8) * 129 + c0 + 1] = acc[mi][ni][3];
        }
    }
    __syncthreads();

#pragma unroll 8
    for (int i = tid; i < 128 * 128; i += 256) {
        int co = i >> 7;
        int ml = i & 127;
        int m  = m0 + ml;
        if (m < M_TOT) {
            int b   = m / PIX;
            int rem = m - b * PIX;
            out[(size_t)b * (COUT * PIX) + (size_t)co * PIX + rem] =
                so[ml * 129 + co] + __ldg(bias + co);
        }
    }
}

// ---------------------------------------------------------------------------
// Launch
// ---------------------------------------------------------------------------
extern "C" void kernel_launch(void* const* d_in, const int* in_sizes, int n_in,
                              void* d_out, int out_size) {
    const float* input  = (const float*)d_in[0];
    const float* offset = (const float*)d_in[1];
    const float* mask   = (const float*)d_in[2];
    const float* weight = (const float*)d_in[3];
    const float* bias   = (const float*)d_in[4];
    float* out = (float*)d_out;

    cudaFuncSetAttribute(gemm_kernel,
                         cudaFuncAttributeMaxDynamicSharedMemorySize, GEMM_SMEM);

    transpose_kernel<<<B_ * H_ * 8, dim3(32, 8)>>>(input);
    prep_weight_kernel<<<(COUT * KDIM + 255) / 256, 256>>>(weight);
    precompute_kernel<<<(NTASK + 255) / 256, 256>>>(offset, mask);
    sample_kernel<<<(M_TOT + 31) / 32, 512>>>();
    gemm_kernel<<<MT, 256, GEMM_SMEM>>>(bias, out);
}